// round 3
// baseline (speedup 1.0000x reference)
#include <cuda_runtime.h>
#include <cstdint>

// SpikeFP32GELUExact: input [B,S,D,32] float32 pulse bits (MSB first) encoding
// fp32 values; output = same pulse encoding of fp32(GELU_tanh_fp64(x)).
//
// Warp-cooperative coalesced pack/unpack (round 2) + minimal-DP-op fp64 GELU:
// custom exp (Cody-Waite + deg-13 Taylor, 2^k scale via integer exponent) and
// Newton reciprocal seeded from fp32 MUFU instead of IEEE DDIV. ~30 DP ops vs
// ~50 with libm exp + DDIV; accuracy ~2^-50 rel, so the fp32-rounded result
// matches the reference fp64 chain for (essentially) every input.

__device__ __forceinline__ double exp_fast(double t, double& /*unused*/) { return t; }

__global__ __launch_bounds__(256) void gelu_pulse_kernel(
    const float* __restrict__ in, float* __restrict__ out, int n_vals)
{
    const unsigned FULL = 0xFFFFFFFFu;
    int gwarp = (int)((blockIdx.x * blockDim.x + threadIdx.x) >> 5);
    int lane  = threadIdx.x & 31;
    if (gwarp * 32 >= n_vals) return;

    size_t base = (size_t)gwarp * 1024;   // 32 values * 32 bits
    const float* p = in + base + lane;

    // ---- coalesced load + ballot pack ----
    uint32_t my_u = 0;
#pragma unroll
    for (int t = 0; t < 32; ++t) {
        float f = p[(size_t)t * 32];
        uint32_t b = __ballot_sync(FULL, f != 0.0f);
        if (lane == t) my_u = b;
    }
    my_u = __brev(my_u);  // pulse bit i has significance 31-i

    // ---- fp64 GELU chain, minimal DP ops ----
    float  xf = __uint_as_float(my_u);
    double x  = (double)xf;                         // exact widen
    double x2 = x * x;
    double x3 = x2 * x;
    double inner = fma(0.044715, x3, x);
    // 2*z with z = round(c*inner): scaling by 2 is exact and commutes with
    // rounding, so 2*round(c*inner) == round((2c)*inner).
    double z2 = 1.5957691216057308 * inner;         // 2 * 0.7978845608028654
    // clamp: for |2z| >= 39 the fp64 tanh saturates so the final fp32 is
    // exact either way; data (N(0,1)) never reaches the clamp.
    z2 = fmin(fmax(z2, -45.0), 45.0);

    // exp(z2): k = round(z2*log2e); r = z2 - k*ln2 (Cody-Waite, fma)
    double tl = z2 * 1.4426950408889634074;
    int    k  = __double2int_rn(tl);
    double kd = (double)k;
    double r  = fma(-kd, 6.93147180369123816490e-01, z2);
    r         = fma(-kd, 1.90821492927058770002e-10, r);
    // degree-13 Taylor Horner (|r| <= 0.3466): truncation ~4e-18
    double pp = 1.6059043836821613e-10;                  // 1/13!
    pp = fma(pp, r, 1.6059043836821613e-10 * 12.0 * 0.0 + 2.0876756987868100e-09); // 1/12!
    pp = fma(pp, r, 2.5052108385441720e-08);             // 1/11!
    pp = fma(pp, r, 2.7557319223985888e-07);             // 1/10!
    pp = fma(pp, r, 2.7557319223985893e-06);             // 1/9!
    pp = fma(pp, r, 2.4801587301587302e-05);             // 1/8!
    pp = fma(pp, r, 1.9841269841269841e-04);             // 1/7!
    pp = fma(pp, r, 1.3888888888888889e-03);             // 1/6!
    pp = fma(pp, r, 8.3333333333333332e-03);             // 1/5!
    pp = fma(pp, r, 4.1666666666666664e-02);             // 1/4!
    pp = fma(pp, r, 1.6666666666666666e-01);             // 1/3!
    pp = fma(pp, r, 0.5);                                // 1/2!
    pp = fma(pp, r, 1.0);
    pp = fma(pp, r, 1.0);
    // scale by 2^k via exponent construction (k in [-65, 65], always normal)
    double scale = __longlong_as_double((long long)(1023 + k) << 52);
    double e2z = pp * scale;

    double num = e2z - 1.0;
    double den = e2z + 1.0;
    // reciprocal: fp32 MUFU seed + 2 fp64 Newton steps (~1 ulp)
    double y = (double)__frcp_rn((float)den);
    y = fma(fma(-den, y, 1.0), y, y);
    y = fma(fma(-den, y, 1.0), y, y);
    double th = num * y;

    double res = 0.5 * (x * (1.0 + th));
    float  rf = (float)res;                         // round-to-nearest down-cast
    uint32_t w = __brev(__float_as_uint(rf));       // bit l of w = pulse bit l

    // ---- coalesced store via shfl broadcast ----
    float* q = out + base + lane;
#pragma unroll
    for (int t = 0; t < 32; ++t) {
        uint32_t wt = __shfl_sync(FULL, w, t);
        q[(size_t)t * 32] = __uint_as_float(((wt >> lane) & 1u) * 0x3F800000u);
    }
}

extern "C" void kernel_launch(void* const* d_in, const int* in_sizes, int n_in,
                              void* d_out, int out_size)
{
    const float* in = (const float*)d_in[0];
    float* out = (float*)d_out;
    int n_vals = in_sizes[0] / 32;   // 32 pulse floats per value
    int threads = 256;               // 8 warps/block, each warp does 32 values
    int warps = (n_vals + 31) / 32;
    int blocks = (warps * 32 + threads - 1) / threads;
    gelu_pulse_kernel<<<blocks, threads>>>(in, out, n_vals);
}

// round 7
// speedup vs baseline: 2.0249x; 2.0249x over previous
#include <cuda_runtime.h>
#include <cstdint>

// SpikeFP32GELUExact: input [B,S,D,32] float32 pulse bits (MSB first) encoding
// fp32 values; output = same pulse encoding of fp32(GELU_tanh_fp64(x)).
//
// Round 4: NO FP64 anywhere. The fp64 GELU chain is reproduced to ~2^-47
// relative accuracy with double-single (two-float) arithmetic on the FP32
// pipe, which is ~60x faster than sm_103a's cut-down DP unit. The final
// result is rounded to fp32, so 2^-47 chain accuracy reproduces the exact
// fp64 pipeline's fp32 output for (essentially) every input.
//
// Conditioning: 1+tanh(z) is computed as u = 2*e2z/(1+e2z) directly — no
// cancellation for either sign (e2z > 0 always), unlike forming tanh ~ -1+eps.

// Compile-time double-single splits of double-precision constants.
#define DS_HI(v) ((float)(v))
#define DS_LO(v) ((float)((v) - (double)(float)(v)))

__device__ __forceinline__ float gelu_exact_ds(float x)
{
    // Tiny |x|: reference's fp64 chain yields exactly 0.5*x (1+tanh rounds
    // to 1). Also preserves the sign of -0.0 (the generic path's final sum
    // would produce +0 for x = -0).
    if (fabsf(x) < 2.8e-17f) return 0.5f * x;

    // ---- x^3 as DS (x^2 is exact in a two-float pair) ----
    float x2h = x * x;
    float x2l = fmaf(x, x, -x2h);
    float x3h = x2h * x;
    float x3l = fmaf(x2h, x, -x3h);
    x3l = fmaf(x2l, x, x3l);

    // ---- inner = x + 0.044715 * x^3 ----
    const float Ch = DS_HI(0.044715);
    const float Cl = DS_LO(0.044715);
    float ph = Ch * x3h;
    float pl = fmaf(Ch, x3h, -ph);
    pl = fmaf(Ch, x3l, pl);
    pl = fmaf(Cl, x3h, pl);
    // two_sum(ph, x) (magnitudes unordered)
    float sh = ph + x;
    float bb = sh - ph;
    float sl = (ph - (sh - bb)) + (x - bb);
    sl += pl;
    float ih = sh + sl;            // renorm (quick: |sl| << |sh| after add)
    float il = sl - (ih - sh);

    // ---- z2 = 2*0.7978845608028654 * inner  (= argument of exp) ----
    const float Kh = DS_HI(2.0 * 0.7978845608028654);
    const float Kl = DS_LO(2.0 * 0.7978845608028654);
    float zh = Kh * ih;
    float zl = fmaf(Kh, ih, -zh);
    zl = fmaf(Kh, il, zl);
    zl = fmaf(Kl, ih, zl);
    // clamp (tanh saturated far before |z2|=45; data never reaches this)
    if (zh > 45.0f)  { zh = 45.0f;  zl = 0.0f; }
    if (zh < -45.0f) { zh = -45.0f; zl = 0.0f; }

    // ---- exp(z2): Cody-Waite reduction, exact pieces ----
    float kf = rintf(zh * 1.44269504f);
    int   k  = (int)kf;
    const float  L1 = 0.693359375f;                    // 9-bit mantissa: k*L1 exact
    const double D1 = 0.6931471805599453;              // fl64(ln2)
    const double D2 = 2.3190468138462996e-17;          // ln2 - fl64(ln2)
    const float  L2f = (float)(D1 - (double)0.693359375f);
    const float  L3f = (float)(((D1 - (double)0.693359375f) - (double)(float)(D1 - (double)0.693359375f)) + D2);

    float t1  = fmaf(-kf, L1, zh);                     // exact (Sterbenz)
    float p1  = kf * L2f;
    float p1e = fmaf(kf, L2f, -p1);                    // two_prod
    // two_sum(t1, -p1)
    float rh  = t1 - p1;
    float b2  = rh - t1;
    float rl  = (t1 - (rh - b2)) + (-p1 - b2);
    rl = ((zl - p1e) - kf * L3f) + rl;
    // renorm via two_sum (rh may be tiny)
    float rhn = rh + rl;
    float b3  = rhn - rh;
    float rln = (rh - (rhn - b3)) + (rl - b3);

    // ---- poly: degrees 13..8 in plain fp32 (error enters * r^8) ----
    float q = 1.60590438e-10f;            // 1/13!
    q = fmaf(q, rhn, 2.08767570e-09f);    // 1/12!
    q = fmaf(q, rhn, 2.50521084e-08f);    // 1/11!
    q = fmaf(q, rhn, 2.75573192e-07f);    // 1/10!
    q = fmaf(q, rhn, 2.75573192e-06f);    // 1/9!
    q = fmaf(q, rhn, 2.48015873e-05f);    // 1/8!   -> h8

    // ---- degrees 7..0 in DS Horner ----
    float hh, hl;
    {   // h7 = c7 + r*h8 (h8 single)
        float gh = rhn * q;
        float gl = fmaf(rhn, q, -gh);
        gl = fmaf(rln, q, gl);
        const float cH = DS_HI(1.9841269841269841e-04), cL = DS_LO(1.9841269841269841e-04);
        float s = cH + gh;
        float e = gh - (s - cH);
        float lo = (cL + gl) + e;
        hh = s + lo;
        hl = lo - (hh - s);
    }
#define POLY_STEP(CH, CL) do { \
        float gh = rhn * hh; \
        float gl = fmaf(rhn, hh, -gh); \
        gl = fmaf(rhn, hl, gl); \
        gl = fmaf(rln, hh, gl); \
        float s = (CH) + gh; \
        float e = gh - (s - (CH)); \
        float lo = ((CL) + gl) + e; \
        hh = s + lo; \
        hl = lo - (hh - s); \
    } while (0)
    POLY_STEP(DS_HI(1.3888888888888889e-03), DS_LO(1.3888888888888889e-03)); // 1/6!
    POLY_STEP(DS_HI(8.3333333333333332e-03), DS_LO(8.3333333333333332e-03)); // 1/5!
    POLY_STEP(DS_HI(4.1666666666666664e-02), DS_LO(4.1666666666666664e-02)); // 1/4!
    POLY_STEP(DS_HI(1.6666666666666666e-01), DS_LO(1.6666666666666666e-01)); // 1/3!
    POLY_STEP(0.5f, 0.0f);                                                    // 1/2!
    POLY_STEP(1.0f, 0.0f);                                                    // 1/1!
    POLY_STEP(1.0f, 0.0f);                                                    // 1/0!
#undef POLY_STEP

    // ---- scale by 2^k (exact): e2z = (hh,hl) * 2^k ----
    float sc = __int_as_float((127 + k) << 23);
    float eh = hh * sc;
    float el = hl * sc;

    // ---- den = 1 + e2z (DS; both positive, no cancellation) ----
    float ds_ = 1.0f + eh;
    float bbd = ds_ - 1.0f;
    float dl  = (1.0f - (ds_ - bbd)) + (eh - bbd);
    dl += el;
    float dhn = ds_ + dl;
    float dln = dl - (dhn - ds_);

    // ---- y = 1/den: frcp seed + one DS Newton with t+t^2 correction ----
    float y0  = __frcp_rn(dhn);
    float pr  = dhn * y0;
    float pre = fmaf(dhn, y0, -pr);
    float th_ = 1.0f - pr;                 // exact (pr within 2^-23 of 1)
    float tl_ = -fmaf(dln, y0, pre);
    float tc  = th_ + tl_;
    float tq  = fmaf(tc, tc, tc);          // t + t^2
    float corr = y0 * tq;
    float yh  = y0 + corr;
    float yl  = corr - (yh - y0);

    // ---- res = x * (e2z * y)   [0.5 * 2 folded away: 0.5*x*(1+tanh) = x*e2z*y] ----
    float uh = eh * yh;
    float ue = fmaf(eh, yh, -uh);
    ue = fmaf(eh, yl, ue);
    ue = fmaf(el, yh, ue);
    float qh = x * uh;
    float qe = fmaf(x, uh, -qh);
    qe = fmaf(x, ue, qe);
    return qh + qe;                        // final fp32 rounding
}

__global__ __launch_bounds__(256) void gelu_pulse_kernel(
    const float* __restrict__ in, float* __restrict__ out, int n_vals)
{
    const unsigned FULL = 0xFFFFFFFFu;
    int gwarp = (int)((blockIdx.x * blockDim.x + threadIdx.x) >> 5);
    int lane  = threadIdx.x & 31;
    if (gwarp * 32 >= n_vals) return;

    size_t base = (size_t)gwarp * 1024;   // 32 values * 32 bits
    const float* p = in + base + lane;

    // ---- coalesced load + ballot pack ----
    uint32_t my_u = 0;
#pragma unroll
    for (int t = 0; t < 32; ++t) {
        float f = p[(size_t)t * 32];
        uint32_t b = __ballot_sync(FULL, f != 0.0f);
        if (lane == t) my_u = b;
    }
    my_u = __brev(my_u);  // pulse bit i has significance 31-i

    float xf = __uint_as_float(my_u);
    float rf = gelu_exact_ds(xf);
    uint32_t w = __brev(__float_as_uint(rf));

    // ---- coalesced store via shfl broadcast ----
    float* qo = out + base + lane;
#pragma unroll
    for (int t = 0; t < 32; ++t) {
        uint32_t wt = __shfl_sync(FULL, w, t);
        qo[(size_t)t * 32] = __uint_as_float(((wt >> lane) & 1u) * 0x3F800000u);
    }
}

extern "C" void kernel_launch(void* const* d_in, const int* in_sizes, int n_in,
                              void* d_out, int out_size)
{
    const float* in = (const float*)d_in[0];
    float* out = (float*)d_out;
    int n_vals = in_sizes[0] / 32;   // 32 pulse floats per value
    int threads = 256;               // 8 warps/block, each warp does 32 values
    int warps = (n_vals + 31) / 32;
    int blocks = (warps * 32 + threads - 1) / threads;
    gelu_pulse_kernel<<<blocks, threads>>>(in, out, n_vals);
}

// round 8
// speedup vs baseline: 2.0265x; 1.0008x over previous
#include <cuda_runtime.h>
#include <cstdint>

// SpikeFP32GELUExact: input [B,S,D,32] float32 pulse bits (MSB first) encoding
// fp32 values; output = same pulse encoding of fp32(GELU_tanh_fp64(x)).
//
// Round 8: 128-bit memory path. Lane l, iter t loads float4 at float offset
// t*128+4l (8 LDG.128 / 8 STG.128 per warp). Each float4 holds 4 pulse bits
// (pulse indices 4*(l%8)+c) of value 4t + l/8. A 3-step shfl_xor butterfly OR
// over each 8-lane group assembles the 32-bit pulse word; lane 8g+t owns value
// 4t+g (a permutation the store side mirrors). GELU itself is the proven
// double-single (two-float) fp32-pipe chain from round 4 (~2^-47 rel, matches
// the reference fp64 pipeline after fp32 rounding).

#define DS_HI(v) ((float)(v))
#define DS_LO(v) ((float)((v) - (double)(float)(v)))

__device__ __forceinline__ float gelu_exact_ds(float x)
{
    if (fabsf(x) < 2.8e-17f) return 0.5f * x;

    // ---- x^3 as DS ----
    float x2h = x * x;
    float x2l = fmaf(x, x, -x2h);
    float x3h = x2h * x;
    float x3l = fmaf(x2h, x, -x3h);
    x3l = fmaf(x2l, x, x3l);

    // ---- inner = x + 0.044715 * x^3 ----
    const float Ch = DS_HI(0.044715);
    const float Cl = DS_LO(0.044715);
    float ph = Ch * x3h;
    float pl = fmaf(Ch, x3h, -ph);
    pl = fmaf(Ch, x3l, pl);
    pl = fmaf(Cl, x3h, pl);
    float sh = ph + x;
    float bb = sh - ph;
    float sl = (ph - (sh - bb)) + (x - bb);
    sl += pl;
    float ih = sh + sl;
    float il = sl - (ih - sh);

    // ---- z2 = 2*0.7978845608028654 * inner ----
    const float Kh = DS_HI(2.0 * 0.7978845608028654);
    const float Kl = DS_LO(2.0 * 0.7978845608028654);
    float zh = Kh * ih;
    float zl = fmaf(Kh, ih, -zh);
    zl = fmaf(Kh, il, zl);
    zl = fmaf(Kl, ih, zl);
    if (zh > 45.0f)  { zh = 45.0f;  zl = 0.0f; }
    if (zh < -45.0f) { zh = -45.0f; zl = 0.0f; }

    // ---- exp(z2): Cody-Waite reduction ----
    float kf = rintf(zh * 1.44269504f);
    int   k  = (int)kf;
    const float  L1 = 0.693359375f;
    const double D1 = 0.6931471805599453;
    const double D2 = 2.3190468138462996e-17;
    const float  L2f = (float)(D1 - (double)0.693359375f);
    const float  L3f = (float)(((D1 - (double)0.693359375f) - (double)(float)(D1 - (double)0.693359375f)) + D2);

    float t1  = fmaf(-kf, L1, zh);
    float p1  = kf * L2f;
    float p1e = fmaf(kf, L2f, -p1);
    float rh  = t1 - p1;
    float b2  = rh - t1;
    float rl  = (t1 - (rh - b2)) + (-p1 - b2);
    rl = ((zl - p1e) - kf * L3f) + rl;
    float rhn = rh + rl;
    float b3  = rhn - rh;
    float rln = (rh - (rhn - b3)) + (rl - b3);

    // ---- poly degrees 13..8 in plain fp32 ----
    float q = 1.60590438e-10f;
    q = fmaf(q, rhn, 2.08767570e-09f);
    q = fmaf(q, rhn, 2.50521084e-08f);
    q = fmaf(q, rhn, 2.75573192e-07f);
    q = fmaf(q, rhn, 2.75573192e-06f);
    q = fmaf(q, rhn, 2.48015873e-05f);

    // ---- degrees 7..0 in DS Horner ----
    float hh, hl;
    {
        float gh = rhn * q;
        float gl = fmaf(rhn, q, -gh);
        gl = fmaf(rln, q, gl);
        const float cH = DS_HI(1.9841269841269841e-04), cL = DS_LO(1.9841269841269841e-04);
        float s = cH + gh;
        float e = gh - (s - cH);
        float lo = (cL + gl) + e;
        hh = s + lo;
        hl = lo - (hh - s);
    }
#define POLY_STEP(CH, CL) do { \
        float gh = rhn * hh; \
        float gl = fmaf(rhn, hh, -gh); \
        gl = fmaf(rhn, hl, gl); \
        gl = fmaf(rln, hh, gl); \
        float s = (CH) + gh; \
        float e = gh - (s - (CH)); \
        float lo = ((CL) + gl) + e; \
        hh = s + lo; \
        hl = lo - (hh - s); \
    } while (0)
    POLY_STEP(DS_HI(1.3888888888888889e-03), DS_LO(1.3888888888888889e-03));
    POLY_STEP(DS_HI(8.3333333333333332e-03), DS_LO(8.3333333333333332e-03));
    POLY_STEP(DS_HI(4.1666666666666664e-02), DS_LO(4.1666666666666664e-02));
    POLY_STEP(DS_HI(1.6666666666666666e-01), DS_LO(1.6666666666666666e-01));
    POLY_STEP(0.5f, 0.0f);
    POLY_STEP(1.0f, 0.0f);
    POLY_STEP(1.0f, 0.0f);
#undef POLY_STEP

    // ---- scale by 2^k ----
    float sc = __int_as_float((127 + k) << 23);
    float eh = hh * sc;
    float el = hl * sc;

    // ---- den = 1 + e2z ----
    float ds_ = 1.0f + eh;
    float bbd = ds_ - 1.0f;
    float dl  = (1.0f - (ds_ - bbd)) + (eh - bbd);
    dl += el;
    float dhn = ds_ + dl;
    float dln = dl - (dhn - ds_);

    // ---- y = 1/den: frcp seed + DS Newton ----
    float y0  = __frcp_rn(dhn);
    float pr  = dhn * y0;
    float pre = fmaf(dhn, y0, -pr);
    float th_ = 1.0f - pr;
    float tl_ = -fmaf(dln, y0, pre);
    float tc  = th_ + tl_;
    float tq  = fmaf(tc, tc, tc);
    float corr = y0 * tq;
    float yh  = y0 + corr;
    float yl  = corr - (yh - y0);

    // ---- res = x * (e2z * y) ----
    float uh = eh * yh;
    float ue = fmaf(eh, yh, -uh);
    ue = fmaf(eh, yl, ue);
    ue = fmaf(el, yh, ue);
    float qh = x * uh;
    float qe = fmaf(x, uh, -qh);
    qe = fmaf(x, ue, qe);
    return qh + qe;
}

__global__ __launch_bounds__(256) void gelu_pulse_kernel(
    const float4* __restrict__ in, float4* __restrict__ out, int n_vals)
{
    const unsigned FULL = 0xFFFFFFFFu;
    int gwarp = (int)((blockIdx.x * blockDim.x + threadIdx.x) >> 5);
    int lane  = threadIdx.x & 31;
    if (gwarp * 32 >= n_vals) return;

    size_t base4 = (size_t)gwarp * 256;    // 1024 floats / 4
    const float4* p = in + base4 + lane;
    int sub = lane & 7;                    // position within 8-lane group

    // ---- 128-bit loads + butterfly pack ----
    // Iter t: lane l loads pulse bits 4*sub..4*sub+3 of value 4t + l/8.
    // Butterfly OR over the 8-lane group assembles the full pulse word; lane
    // with (lane&7)==t keeps it -> lane l owns value V(l) = 4*(l%8) + l/8.
    uint32_t myw = 0;
#pragma unroll
    for (int t = 0; t < 8; ++t) {
        float4 f = p[(size_t)t * 32];
        uint32_t nib = ((f.x != 0.0f) ? 1u : 0u)
                     | ((f.y != 0.0f) ? 2u : 0u)
                     | ((f.z != 0.0f) ? 4u : 0u)
                     | ((f.w != 0.0f) ? 8u : 0u);
        uint32_t wrd = nib << (4 * sub);
        wrd |= __shfl_xor_sync(FULL, wrd, 1);
        wrd |= __shfl_xor_sync(FULL, wrd, 2);
        wrd |= __shfl_xor_sync(FULL, wrd, 4);
        if (sub == t) myw = wrd;
    }

    // pulse word -> value bits (pulse bit i has significance 31-i)
    float xf = __uint_as_float(__brev(myw));
    float rf = gelu_exact_ds(xf);
    uint32_t wp = __brev(__float_as_uint(rf));   // back to pulse-bit order

    // ---- 128-bit stores ----
    // Iter t: lane l needs pulse word of value 4t + l/8, held by lane
    // 8*(l/8) + t (ownership permutation above).
    float4* qo = out + base4 + lane;
#pragma unroll
    for (int t = 0; t < 8; ++t) {
        uint32_t wt = __shfl_sync(FULL, wp, (lane & 24) | t);
        uint32_t nib = wt >> (4 * sub);
        float4 o;
        o.x = __uint_as_float((nib & 1u)        * 0x3F800000u);
        o.y = __uint_as_float(((nib >> 1) & 1u) * 0x3F800000u);
        o.z = __uint_as_float(((nib >> 2) & 1u) * 0x3F800000u);
        o.w = __uint_as_float(((nib >> 3) & 1u) * 0x3F800000u);
        qo[(size_t)t * 32] = o;
    }
}

extern "C" void kernel_launch(void* const* d_in, const int* in_sizes, int n_in,
                              void* d_out, int out_size)
{
    const float4* in = (const float4*)d_in[0];
    float4* out = (float4*)d_out;
    int n_vals = in_sizes[0] / 32;   // 32 pulse floats per value
    int threads = 256;               // 8 warps/block, each warp does 32 values
    int warps = (n_vals + 31) / 32;
    int blocks = (warps * 32 + threads - 1) / threads;
    gelu_pulse_kernel<<<blocks, threads>>>(in, out, n_vals);
}

// round 9
// speedup vs baseline: 2.0290x; 1.0012x over previous
#include <cuda_runtime.h>
#include <cstdint>

// SpikeFP32GELUExact: input [B,S,D,32] float32 pulse bits (MSB first) encoding
// fp32 values; output = same pulse encoding of fp32(GELU_tanh_fp64(x)).
//
// Round 9: round-8 128-bit butterfly kernel + streaming cache hints
// (__ldcs/__stcs: 1GB working set >> L2, evict-first reduces LTS churn) and
// 512-thread blocks to recover occupancy / wave balance. GELU is the proven
// double-single (two-float) fp32-pipe chain (~2^-47 rel; matches the
// reference fp64 pipeline after final fp32 rounding).

#define DS_HI(v) ((float)(v))
#define DS_LO(v) ((float)((v) - (double)(float)(v)))

__device__ __forceinline__ float gelu_exact_ds(float x)
{
    if (fabsf(x) < 2.8e-17f) return 0.5f * x;

    // ---- x^3 as DS ----
    float x2h = x * x;
    float x2l = fmaf(x, x, -x2h);
    float x3h = x2h * x;
    float x3l = fmaf(x2h, x, -x3h);
    x3l = fmaf(x2l, x, x3l);

    // ---- inner = x + 0.044715 * x^3 ----
    const float Ch = DS_HI(0.044715);
    const float Cl = DS_LO(0.044715);
    float ph = Ch * x3h;
    float pl = fmaf(Ch, x3h, -ph);
    pl = fmaf(Ch, x3l, pl);
    pl = fmaf(Cl, x3h, pl);
    float sh = ph + x;
    float bb = sh - ph;
    float sl = (ph - (sh - bb)) + (x - bb);
    sl += pl;
    float ih = sh + sl;
    float il = sl - (ih - sh);

    // ---- z2 = 2*0.7978845608028654 * inner ----
    const float Kh = DS_HI(2.0 * 0.7978845608028654);
    const float Kl = DS_LO(2.0 * 0.7978845608028654);
    float zh = Kh * ih;
    float zl = fmaf(Kh, ih, -zh);
    zl = fmaf(Kh, il, zl);
    zl = fmaf(Kl, ih, zl);
    if (zh > 45.0f)  { zh = 45.0f;  zl = 0.0f; }
    if (zh < -45.0f) { zh = -45.0f; zl = 0.0f; }

    // ---- exp(z2): Cody-Waite reduction ----
    float kf = rintf(zh * 1.44269504f);
    int   k  = (int)kf;
    const float  L1 = 0.693359375f;
    const double D1 = 0.6931471805599453;
    const double D2 = 2.3190468138462996e-17;
    const float  L2f = (float)(D1 - (double)0.693359375f);
    const float  L3f = (float)(((D1 - (double)0.693359375f) - (double)(float)(D1 - (double)0.693359375f)) + D2);

    float t1  = fmaf(-kf, L1, zh);
    float p1  = kf * L2f;
    float p1e = fmaf(kf, L2f, -p1);
    float rh  = t1 - p1;
    float b2  = rh - t1;
    float rl  = (t1 - (rh - b2)) + (-p1 - b2);
    rl = ((zl - p1e) - kf * L3f) + rl;
    float rhn = rh + rl;
    float b3  = rhn - rh;
    float rln = (rh - (rhn - b3)) + (rl - b3);

    // ---- poly degrees 13..8 in plain fp32 ----
    float q = 1.60590438e-10f;
    q = fmaf(q, rhn, 2.08767570e-09f);
    q = fmaf(q, rhn, 2.50521084e-08f);
    q = fmaf(q, rhn, 2.75573192e-07f);
    q = fmaf(q, rhn, 2.75573192e-06f);
    q = fmaf(q, rhn, 2.48015873e-05f);

    // ---- degrees 7..0 in DS Horner ----
    float hh, hl;
    {
        float gh = rhn * q;
        float gl = fmaf(rhn, q, -gh);
        gl = fmaf(rln, q, gl);
        const float cH = DS_HI(1.9841269841269841e-04), cL = DS_LO(1.9841269841269841e-04);
        float s = cH + gh;
        float e = gh - (s - cH);
        float lo = (cL + gl) + e;
        hh = s + lo;
        hl = lo - (hh - s);
    }
#define POLY_STEP(CH, CL) do { \
        float gh = rhn * hh; \
        float gl = fmaf(rhn, hh, -gh); \
        gl = fmaf(rhn, hl, gl); \
        gl = fmaf(rln, hh, gl); \
        float s = (CH) + gh; \
        float e = gh - (s - (CH)); \
        float lo = ((CL) + gl) + e; \
        hh = s + lo; \
        hl = lo - (hh - s); \
    } while (0)
    POLY_STEP(DS_HI(1.3888888888888889e-03), DS_LO(1.3888888888888889e-03));
    POLY_STEP(DS_HI(8.3333333333333332e-03), DS_LO(8.3333333333333332e-03));
    POLY_STEP(DS_HI(4.1666666666666664e-02), DS_LO(4.1666666666666664e-02));
    POLY_STEP(DS_HI(1.6666666666666666e-01), DS_LO(1.6666666666666666e-01));
    POLY_STEP(0.5f, 0.0f);
    POLY_STEP(1.0f, 0.0f);
    POLY_STEP(1.0f, 0.0f);
#undef POLY_STEP

    // ---- scale by 2^k ----
    float sc = __int_as_float((127 + k) << 23);
    float eh = hh * sc;
    float el = hl * sc;

    // ---- den = 1 + e2z ----
    float ds_ = 1.0f + eh;
    float bbd = ds_ - 1.0f;
    float dl  = (1.0f - (ds_ - bbd)) + (eh - bbd);
    dl += el;
    float dhn = ds_ + dl;
    float dln = dl - (dhn - ds_);

    // ---- y = 1/den: frcp seed + DS Newton ----
    float y0  = __frcp_rn(dhn);
    float pr  = dhn * y0;
    float pre = fmaf(dhn, y0, -pr);
    float th_ = 1.0f - pr;
    float tl_ = -fmaf(dln, y0, pre);
    float tc  = th_ + tl_;
    float tq  = fmaf(tc, tc, tc);
    float corr = y0 * tq;
    float yh  = y0 + corr;
    float yl  = corr - (yh - y0);

    // ---- res = x * (e2z * y) ----
    float uh = eh * yh;
    float ue = fmaf(eh, yh, -uh);
    ue = fmaf(eh, yl, ue);
    ue = fmaf(el, yh, ue);
    float qh = x * uh;
    float qe = fmaf(x, uh, -qh);
    qe = fmaf(x, ue, qe);
    return qh + qe;
}

__global__ __launch_bounds__(512) void gelu_pulse_kernel(
    const float4* __restrict__ in, float4* __restrict__ out, int n_vals)
{
    const unsigned FULL = 0xFFFFFFFFu;
    int gwarp = (int)((blockIdx.x * blockDim.x + threadIdx.x) >> 5);
    int lane  = threadIdx.x & 31;
    if (gwarp * 32 >= n_vals) return;

    size_t base4 = (size_t)gwarp * 256;    // 1024 floats / 4
    const float4* p = in + base4 + lane;
    int sub = lane & 7;                    // position within 8-lane group

    // ---- 128-bit streaming loads + butterfly pack ----
    // Iter t: lane l loads pulse bits 4*sub..4*sub+3 of value 4t + l/8.
    // Butterfly OR over the 8-lane group assembles the full pulse word; lane
    // with (lane&7)==t keeps it -> lane l owns value V(l) = 4*(l%8) + l/8.
    uint32_t myw = 0;
#pragma unroll
    for (int t = 0; t < 8; ++t) {
        float4 f = __ldcs(p + (size_t)t * 32);
        uint32_t nib = ((f.x != 0.0f) ? 1u : 0u)
                     | ((f.y != 0.0f) ? 2u : 0u)
                     | ((f.z != 0.0f) ? 4u : 0u)
                     | ((f.w != 0.0f) ? 8u : 0u);
        uint32_t wrd = nib << (4 * sub);
        wrd |= __shfl_xor_sync(FULL, wrd, 1);
        wrd |= __shfl_xor_sync(FULL, wrd, 2);
        wrd |= __shfl_xor_sync(FULL, wrd, 4);
        if (sub == t) myw = wrd;
    }

    // pulse word -> value bits (pulse bit i has significance 31-i)
    float xf = __uint_as_float(__brev(myw));
    float rf = gelu_exact_ds(xf);
    uint32_t wp = __brev(__float_as_uint(rf));   // back to pulse-bit order

    // ---- 128-bit streaming stores ----
    // Iter t: lane l needs pulse word of value 4t + l/8, held by lane
    // 8*(l/8) + t (ownership permutation above).
    float4* qo = out + base4 + lane;
#pragma unroll
    for (int t = 0; t < 8; ++t) {
        uint32_t wt = __shfl_sync(FULL, wp, (lane & 24) | t);
        uint32_t nib = wt >> (4 * sub);
        float4 o;
        o.x = __uint_as_float((nib & 1u)        * 0x3F800000u);
        o.y = __uint_as_float(((nib >> 1) & 1u) * 0x3F800000u);
        o.z = __uint_as_float(((nib >> 2) & 1u) * 0x3F800000u);
        o.w = __uint_as_float(((nib >> 3) & 1u) * 0x3F800000u);
        __stcs(qo + (size_t)t * 32, o);
    }
}

extern "C" void kernel_launch(void* const* d_in, const int* in_sizes, int n_in,
                              void* d_out, int out_size)
{
    const float4* in = (const float4*)d_in[0];
    float4* out = (float4*)d_out;
    int n_vals = in_sizes[0] / 32;   // 32 pulse floats per value
    int threads = 512;               // 16 warps/block, each warp does 32 values
    int warps = (n_vals + 31) / 32;
    int blocks = (warps * 32 + threads - 1) / threads;
    gelu_pulse_kernel<<<blocks, threads>>>(in, out, n_vals);
}